// round 1
// baseline (speedup 1.0000x reference)
#include <cuda_runtime.h>
#include <cuda_bf16.h>
#include <cstdint>

#define N_SEGMENTS 50000
#define N_FEAT 64          // floats per row
#define N_ROWS 1600000

// Flag: 1 if index buffer is int64, 0 if int32. Written by detect kernel,
// read by the aggregation kernel. Deterministic for fixed inputs.
__device__ int g_idx_is64;

// ---------------------------------------------------------------------------
// Detect index dtype: if the buffer is int64 (values < 50000), every odd
// 32-bit word is the zero high-half. With int32 data, odd words are random
// indices in [0, 50000); probability all 32 sampled odd words are zero is
// (1/50000)^32 ~ 0.
// ---------------------------------------------------------------------------
__global__ void detect_idx_kernel(const unsigned int* __restrict__ idx_words) {
    if (threadIdx.x == 0 && blockIdx.x == 0) {
        int all_zero = 1;
        #pragma unroll
        for (int i = 1; i < 64; i += 2) {
            if (idx_words[i] != 0u) all_zero = 0;
        }
        g_idx_is64 = all_zero;
    }
}

// ---------------------------------------------------------------------------
// Zero the output (harness poisons it with 0xAA).
// out has N_SEGMENTS * 64 floats = 3.2M floats = 800K float4.
// ---------------------------------------------------------------------------
__global__ void zero_out_kernel(float4* __restrict__ out, int n_vec4) {
    int i = blockIdx.x * blockDim.x + threadIdx.x;
    if (i < n_vec4) {
        out[i] = make_float4(0.f, 0.f, 0.f, 0.f);
    }
}

// ---------------------------------------------------------------------------
// Scatter-add: 16 lanes cooperate on one input row.
// Each lane loads one float4 (16B) -> 16 lanes x 16B = 256B = one full row,
// perfectly coalesced. Each lane issues one red.global.add.v4.f32 (no return,
// resolves in L2) to the segment's output row.
// ---------------------------------------------------------------------------
__global__ void __launch_bounds__(256)
aggr_kernel(const float4* __restrict__ in,
            const void* __restrict__ idx_raw,
            float* __restrict__ out,
            int n_rows) {
    const int is64 = g_idx_is64;
    const long long gtid = (long long)blockIdx.x * blockDim.x + threadIdx.x;
    const int row = (int)(gtid >> 4);       // 16 lanes per row
    const int lane = (int)(gtid & 15);

    if (row >= n_rows) return;

    long long seg;
    if (is64) {
        seg = ((const long long*)idx_raw)[row];
    } else {
        seg = (long long)((const int*)idx_raw)[row];
    }

    // Load this lane's 16 bytes of the row.
    float4 v = in[(long long)row * (N_FEAT / 4) + lane];

    float* dst = out + seg * N_FEAT + lane * 4;
    asm volatile(
        "red.global.add.v4.f32 [%0], {%1, %2, %3, %4};"
        :: "l"(dst), "f"(v.x), "f"(v.y), "f"(v.z), "f"(v.w)
        : "memory");
}

// ---------------------------------------------------------------------------
// Launch
// ---------------------------------------------------------------------------
extern "C" void kernel_launch(void* const* d_in, const int* in_sizes, int n_in,
                              void* d_out, int out_size) {
    const float4* in   = (const float4*)d_in[0];
    const void*   idx  = (const void*)d_in[1];
    float*        out  = (float*)d_out;

    const int n_rows = in_sizes[1];         // 1,600,000 index entries (element count)

    // 1) detect index dtype (int32 vs int64)
    detect_idx_kernel<<<1, 32>>>((const unsigned int*)idx);

    // 2) zero output
    const int n_vec4 = out_size / 4;        // 3.2M floats -> 800K float4
    zero_out_kernel<<<(n_vec4 + 255) / 256, 256>>>((float4*)d_out, n_vec4);

    // 3) scatter-add
    const long long total_threads = (long long)n_rows * 16;
    const int threads = 256;
    const int blocks = (int)((total_threads + threads - 1) / threads);
    aggr_kernel<<<blocks, threads>>>(in, idx, out, n_rows);
}